// round 17
// baseline (speedup 1.0000x reference)
#include <cuda_runtime.h>
#include <cuda_bf16.h>
#include <cstdint>

// ---------------- problem constants ----------------
#define BATCH 2
#define NQ    4096
#define NPTS  8192
#define DIM   256
#define KNN_K 16
#define KG2   8
#define NB    25
#define XROWS 204800            // BATCH*NQ*NB
#define POSROWS 196608          // BATCH*NQ*24
#define FLT_BIG 3.402823466e+38f

// ---------------- scratch (device globals; no allocations) ----------------
__device__ float g_kp [BATCH * NPTS * DIM];      // points @ (w_ks@gw1)
__device__ float g_vp [BATCH * NPTS * DIM];      // points @ w_vs
__device__ float g_gk [BATCH * NQ * KG2 * DIM];  // sgf @ (w_kc@gw1)
__device__ float g_gv [BATCH * NQ * KG2 * DIM];  // sgf @ w_vc
__device__ float g_qa [BATCH * DIM];
__device__ float g_kgl[BATCH * DIM];
__device__ float g_vgl[BATCH * DIM];
__device__ float g_qag1[BATCH * DIM];            // qa @ gw1
__device__ float g_a124[BATCH * DIM];            // relu((qa-kgl)@gw1+gb1)
__device__ float g_cvec[DIM];                    // db2@gw1 + gb1
__device__ float g_Wc [3 * 65536];               // 0=w_ks@gw1 1=w_kc@gw1 2=dw2@gw1
__device__ int   g_knn[BATCH * NQ * KNN_K];
__device__ float g_db [BATCH * NQ * 24 * 4];
__device__ float g_V  [(size_t)XROWS * DIM];
__device__ float g_Xf [(size_t)XROWS * DIM];     // gamma2 output (logits)
// packed bf16 hi/lo A-operand planes: layout ((plane*8 + chunk)*Mtot + row)*80 + (col%32)*2
__device__ char  g_A1pack[(size_t)2 * 8 * XROWS * 80];
__device__ char  g_Ppack [(size_t)2 * 8 * (BATCH * NPTS) * 80];
__device__ char  g_Spack [(size_t)2 * 8 * (BATCH * NQ * KG2) * 80];
// prepacked weights: 7 slots x 8 k-chunks x 2 n-blocks, each region =
// [hi: 128 n-rows x 40 bf16][lo: same] = 20480 B
__device__ uint4 g_Bpack[7 * 8 * 2 * 1280];

// ---------------- PTX helpers (portable, no 'a'-gated features) ----------------
#define LDM_X4(r0, r1, r2, r3, addr) \
    asm volatile("ldmatrix.sync.aligned.m8n8.x4.shared.b16 {%0,%1,%2,%3}, [%4];" \
        : "=r"(r0), "=r"(r1), "=r"(r2), "=r"(r3) : "r"(addr))

#define MMA16816(d, a, b) \
    asm volatile("mma.sync.aligned.m16n8k16.row.col.f32.bf16.bf16.f32 " \
        "{%0,%1,%2,%3}, {%4,%5,%6,%7}, {%8,%9}, {%0,%1,%2,%3};" \
        : "+f"((d)[0]), "+f"((d)[1]), "+f"((d)[2]), "+f"((d)[3]) \
        : "r"((a)[0]), "r"((a)[1]), "r"((a)[2]), "r"((a)[3]), \
          "r"((b)[0]), "r"((b)[1]))

#define CP_ASYNC16(dst, src) \
    asm volatile("cp.async.cg.shared.global [%0], [%1], 16;" :: "r"(dst), "l"(src))
#define CP_COMMIT() asm volatile("cp.async.commit_group;" ::: "memory")
#define CP_WAIT1()  asm volatile("cp.async.wait_group 1;" ::: "memory")
#define CP_WAIT0()  asm volatile("cp.async.wait_group 0;" ::: "memory")

__device__ __forceinline__ uint32_t smem_u32(const void* p) {
    uint32_t a;
    asm("{ .reg .u64 t; cvta.to.shared.u64 t, %1; cvt.u32.u64 %0, t; }" : "=r"(a) : "l"(p));
    return a;
}

// two fp32 -> packed bf16 hi pair + lo (residual) pair
__device__ __forceinline__ void split2(float a, float b, uint32_t& h, uint32_t& l) {
    __nv_bfloat16 ha = __float2bfloat16(a), hb = __float2bfloat16(b);
    float ra = a - __bfloat162float(ha);
    float rb = b - __bfloat162float(hb);
    h = (uint32_t)__bfloat16_as_ushort(ha) | ((uint32_t)__bfloat16_as_ushort(hb) << 16);
    __nv_bfloat16 la = __float2bfloat16(ra), lb = __float2bfloat16(rb);
    l = (uint32_t)__bfloat16_as_ushort(la) | ((uint32_t)__bfloat16_as_ushort(lb) << 16);
}

// packed-plane byte offset
__device__ __forceinline__ size_t pk_off(int plane, int chunk, size_t Mtot, size_t row, int within) {
    return ((size_t)(plane * 8 + chunk) * Mtot + row) * 80 + (size_t)within * 2;
}

// SMEM stage layout (bytes): [A_hi 5120][A_lo 5120][B_hi 10240][B_lo 10240]
#define STG   30720
#define SA_LO 5120
#define SB_HI 10240
#define SMEM_DYN (3 * STG)

// ---------------- KNN: warp-cooperative, one warp per query ----------------
__global__ __launch_bounds__(256)
void knn_kernel(const float* __restrict__ xyz_q, const float* __restrict__ xyz) {
    const int b    = blockIdx.y;
    const int tid  = threadIdx.x;
    const int lane = tid & 31;
    const int w    = tid >> 5;
    const int q    = blockIdx.x * 8 + w;

    __shared__ float4 sp[1024];

    const size_t qb = (size_t)(b * NQ + q) * 3;
    const float qx = xyz_q[qb + 0], qy = xyz_q[qb + 1], qz = xyz_q[qb + 2];
    const float qq = qx * qx + qy * qy + qz * qz;

    float vd = FLT_BIG;
    int   vi = 0x7fffffff;
    float maxd = FLT_BIG;
    int   maxi = 0x7fffffff;

    for (int tile = 0; tile < 8; ++tile) {
        const int t0 = tile * 1024;
        __syncthreads();
        for (int i = tid; i < 1024; i += 256) {
            const size_t pb = (size_t)(b * NPTS + t0 + i) * 3;
            float x = xyz[pb + 0], y = xyz[pb + 1], z = xyz[pb + 2];
            sp[i] = make_float4(x, y, z, x * x + y * y + z * z);
        }
        __syncthreads();
        for (int i = 0; i < 1024; i += 32) {
            const float4 P = sp[i + lane];
            const float dot = qx * P.x + qy * P.y + qz * P.z;
            const float d2  = (qq + P.w) - 2.0f * dot;
            const int   ci  = t0 + i + lane;
            const bool pass = (d2 < maxd) || (d2 == maxd && ci < maxi);
            unsigned m = __ballot_sync(0xffffffffu, pass);
            while (m) {
                const int src = __ffs(m) - 1;
                m &= m - 1;
                const float dn = __shfl_sync(0xffffffffu, d2, src);
                const int   in = __shfl_sync(0xffffffffu, ci, src);
                if (dn < maxd || (dn == maxd && in < maxi)) {
                    const float sdv = __shfl_up_sync(0xffffffffu, vd, 1);
                    const int   siv = __shfl_up_sync(0xffffffffu, vi, 1);
                    const bool gt = (dn < vd) || (dn == vd && in < vi);
                    const unsigned bb = __ballot_sync(0xffffffffu, gt);
                    const int pos = __ffs(bb) - 1;
                    if (gt) {
                        vd = (lane == pos) ? dn : sdv;
                        vi = (lane == pos) ? in : siv;
                    }
                    maxd = __shfl_sync(0xffffffffu, vd, 31);
                    maxi = __shfl_sync(0xffffffffu, vi, 31);
                }
            }
        }
    }
    if (lane < KNN_K)
        g_knn[(size_t)(b * NQ + q) * KNN_K + lane] = vi;
}

// ---------------- combined-weight precompute: g_Wc[z] = A_z @ gw1 (fp32) ------
__global__ __launch_bounds__(256)
void wcomb_kernel(const float* __restrict__ w_ks, const float* __restrict__ w_kc,
                  const float* __restrict__ dw2, const float* __restrict__ gw1) {
    __shared__ float As[16][64];
    __shared__ float Ws[16][64];
    const float* Asrc = (blockIdx.z == 0) ? w_ks : (blockIdx.z == 1) ? w_kc : dw2;
    float* C = g_Wc + (size_t)blockIdx.z * 65536;
    const int tid = threadIdx.x;
    const int m0 = blockIdx.y * 64, n0 = blockIdx.x * 64;
    const int arow = tid >> 2, acol = (tid & 3) << 2;
    const int wrow = tid >> 4, wcol = (tid & 15) << 2;
    const int ty = tid >> 4, tx = tid & 15;
    float acc[4][4] = {};
    for (int kk = 0; kk < 256; kk += 16) {
        const float4 pa = *(const float4*)(Asrc + (size_t)(m0 + arow) * 256 + kk + acol);
        const float4 pw = *(const float4*)(gw1 + (size_t)(kk + wrow) * 256 + n0 + wcol);
        As[acol + 0][arow] = pa.x; As[acol + 1][arow] = pa.y;
        As[acol + 2][arow] = pa.z; As[acol + 3][arow] = pa.w;
        *(float4*)&Ws[wrow][wcol] = pw;
        __syncthreads();
#pragma unroll
        for (int k = 0; k < 16; ++k) {
            const float4 ra = *(const float4*)&As[k][ty << 2];
            const float4 rb = *(const float4*)&Ws[k][tx << 2];
            acc[0][0]=fmaf(ra.x,rb.x,acc[0][0]); acc[0][1]=fmaf(ra.x,rb.y,acc[0][1]);
            acc[0][2]=fmaf(ra.x,rb.z,acc[0][2]); acc[0][3]=fmaf(ra.x,rb.w,acc[0][3]);
            acc[1][0]=fmaf(ra.y,rb.x,acc[1][0]); acc[1][1]=fmaf(ra.y,rb.y,acc[1][1]);
            acc[1][2]=fmaf(ra.y,rb.z,acc[1][2]); acc[1][3]=fmaf(ra.y,rb.w,acc[1][3]);
            acc[2][0]=fmaf(ra.z,rb.x,acc[2][0]); acc[2][1]=fmaf(ra.z,rb.y,acc[2][1]);
            acc[2][2]=fmaf(ra.z,rb.z,acc[2][2]); acc[2][3]=fmaf(ra.z,rb.w,acc[2][3]);
            acc[3][0]=fmaf(ra.w,rb.x,acc[3][0]); acc[3][1]=fmaf(ra.w,rb.y,acc[3][1]);
            acc[3][2]=fmaf(ra.w,rb.z,acc[3][2]); acc[3][3]=fmaf(ra.w,rb.w,acc[3][3]);
        }
        __syncthreads();
    }
#pragma unroll
    for (int i = 0; i < 4; ++i)
        *(float4*)(C + (size_t)(m0 + (ty << 2) + i) * 256 + n0 + (tx << 2)) =
            make_float4(acc[i][0], acc[i][1], acc[i][2], acc[i][3]);
}

// ---------------- tiny projections ----------------
__global__ __launch_bounds__(256)
void proj_small_kernel(const float* __restrict__ lat,
                       const float* __restrict__ w_qs,
                       const float* __restrict__ w_kg,
                       const float* __restrict__ w_vg) {
    const int b = blockIdx.x, t = threadIdx.x;
    __shared__ float ls[DIM];
    ls[t] = lat[b * DIM + t];
    __syncthreads();
    float aq = 0.f, ak = 0.f, av = 0.f;
    for (int i = 0; i < DIM; ++i) {
        const float l = ls[i];
        aq = fmaf(l, w_qs[i * DIM + t], aq);
        ak = fmaf(l, w_kg[i * DIM + t], ak);
        av = fmaf(l, w_vg[i * DIM + t], av);
    }
    g_qa [b * DIM + t] = aq;
    g_kgl[b * DIM + t] = ak;
    g_vgl[b * DIM + t] = av;
}

// proj2: qag1 = qa@gw1; a124 = relu((qa-kgl)@gw1 + gb1); cvec = db2@gw1 + gb1
__global__ __launch_bounds__(256)
void proj2_kernel(const float* __restrict__ gw1, const float* __restrict__ gb1,
                  const float* __restrict__ db2) {
    const int b = blockIdx.x, t = threadIdx.x;
    __shared__ float sq[DIM], sk[DIM];
    sq[t] = g_qa[b * DIM + t];
    sk[t] = g_kgl[b * DIM + t];
    __syncthreads();
    float aq = 0.f, ax = 0.f, cv = 0.f;
    for (int i = 0; i < DIM; ++i) {
        const float w = gw1[i * DIM + t];
        aq = fmaf(sq[i], w, aq);
        ax = fmaf(sq[i] - sk[i], w, ax);
        if (b == 0) cv = fmaf(db2[i], w, cv);
    }
    g_qag1[b * DIM + t] = aq;
    g_a124[b * DIM + t] = fmaxf(ax + gb1[t], 0.f);
    if (b == 0) g_cvec[t] = cv + gb1[t];
}

// ---------------- weight prepack ----------------
__global__ __launch_bounds__(256)
void prepack_kernel(const float* __restrict__ w0, const float* __restrict__ w1,
                    const float* __restrict__ w2, const float* __restrict__ w3,
                    const float* __restrict__ w4, const float* __restrict__ w5,
                    const float* __restrict__ w6) {
    const float* Ws[7] = {w0, w1, w2, w3, w4, w5, w6};
    const int bid = blockIdx.x;
    const int w = bid >> 4, kc = (bid >> 1) & 7, nblk = bid & 1;
    const float* W = Ws[w];
    char* dst = (char*)g_Bpack + (size_t)bid * 20480;
#pragma unroll
    for (int i = 0; i < 16; ++i) {
        const int idx = threadIdx.x + i * 256;
        const int n_local = idx >> 5, k_local = idx & 31;
        const int n = nblk * 128 + n_local;
        const int k = kc * 32 + k_local;
        const float x = W[(size_t)k * 256 + n];
        __nv_bfloat16 h = __float2bfloat16(x);
        float lo = x - __bfloat162float(h);
        *(__nv_bfloat16*)(dst + n_local * 80 + k_local * 2)         = h;
        *(__nv_bfloat16*)(dst + 10240 + n_local * 80 + k_local * 2) = __float2bfloat16(lo);
    }
}

// ---------------- A prepack: fp32 [M,256] -> hi/lo plane format ----------------
__global__ __launch_bounds__(256)
void pack_a_kernel(const float* __restrict__ A, char* __restrict__ dst, int Mtot) {
    const size_t row = (size_t)blockIdx.x * 2 + (threadIdx.x >> 7);
    const int cp = threadIdx.x & 127;
    const int col = cp * 2;
    const float2 v = *(const float2*)(A + row * 256 + col);
    uint32_t h, l;
    split2(v.x, v.y, h, l);
    const int chunk = col >> 5, within = col & 31;
    *(uint32_t*)(dst + pk_off(0, chunk, (size_t)Mtot, row, within)) = h;
    *(uint32_t*)(dst + pk_off(1, chunk, (size_t)Mtot, row, within)) = l;
}

// ---------------- db + global-token row24 (V + packed A1) ----------------
__global__ __launch_bounds__(256)
void db_kernel(const float* __restrict__ xyz_q,
               const float* __restrict__ xyz,
               const float* __restrict__ closest) {
    const int bq = blockIdx.x;
    const int b  = bq >> 12;
    const int t  = threadIdx.x;
    __shared__ int   knn_s[KNN_K];
    __shared__ float q3[3];
    if (t < KNN_K) knn_s[t] = g_knn[(size_t)bq * KNN_K + t];
    if (t < 3)     q3[t]    = xyz_q[(size_t)bq * 3 + t];
    __syncthreads();

    if (t < 72) {
        const int j = t / 3, d = t % 3;
        float src;
        if (j < KNN_K) src = xyz[(size_t)(b * NPTS + knn_s[j]) * 3 + d];
        else           src = closest[((size_t)bq * KG2 + (j - KNN_K)) * 3 + d];
        g_db[(size_t)(bq * 24 + j) * 4 + d] = q3[d] - src;
    }
    // global token row24: A1 = a124 (per batch, packed), V = vgl
    const size_t grow = (size_t)bq * NB + 24;
    if (t < 128) {
        const int col = t * 2;
        const float2 a2 = *(const float2*)(g_a124 + b * 256 + col);
        uint32_t h, l;
        split2(a2.x, a2.y, h, l);
        const int chunk = col >> 5, within = col & 31;
        *(uint32_t*)(g_A1pack + pk_off(0, chunk, XROWS, grow, within)) = h;
        *(uint32_t*)(g_A1pack + pk_off(1, chunk, XROWS, grow, within)) = l;
    }
    g_V[grow * 256 + t] = g_vgl[b * 256 + t];
}

// ---------------- cp.async mma GEMM: C[M x 256] = A @ W (bf16x3) ----------------
// CTA tile M64 x N128; DUAL=1: blockIdx.y in 0..3 encodes (weight, n-half).
// ASRC 0: A from packed planes.  ASRC 1: A = relu(d @ W1 + b1) from g_db.
// EPI 0: C = acc (+bias) fp32 (C0/C1 by weight).  EPI 2: hidden dual epilogue:
//   gsel 0 (dw2): V[grow] = gathered v + acc + db2
//   gsel 1 (dw2@gw1): A1pack[grow] = relu(qag1 - gathered kg1 + acc + cvec)
template<int ASRC, int EPI, int DUAL>
__global__ __launch_bounds__(256, 2)
void gemm_cp_kernel(const char* __restrict__ Apack, size_t Mtot, int widx_base,
                    const float* __restrict__ bias,
                    float* __restrict__ C0, float* __restrict__ C1,
                    const float* __restrict__ W1, const float* __restrict__ b1) {
    extern __shared__ char smem_dyn[];
    const uint32_t sb0 = smem_u32(smem_dyn);
    const int tid = threadIdx.x, lane = tid & 31, wid = tid >> 5;
    const int warp_n = wid & 3, warp_m = wid >> 2;
    const size_t m0 = (size_t)blockIdx.x * 64;
    const int yy = blockIdx.y;
    const int nhalf = DUAL ? (yy & 1) : yy;
    const int gsel  = DUAL ? (yy >> 1) : 0;
    const int widx  = widx_base + gsel;
    const int n0 = nhalf * 128;

    const char* bbase = (const char*)g_Bpack + ((size_t)(widx * 8) * 2 + nhalf) * 20480;

    float acc[2][4][4];
#pragma unroll
    for (int mt = 0; mt < 2; ++mt)
#pragma unroll
        for (int nt = 0; nt < 4; ++nt)
#pragma unroll
            for (int j = 0; j < 4; ++j) acc[mt][nt][j] = 0.f;

    const int arow = tid >> 2, kq = (tid & 3) * 8;
    float4 dd;
    if (ASRC == 1) dd = *(const float4*)(g_db + (m0 + arow) * 4);

#define ISSUE_CHUNK(c_, buf_) do {                                              \
        const char* bsrc_ = bbase + (size_t)(c_) * 40960;                       \
        const uint32_t bdst_ = sb0 + (buf_) * STG + SB_HI;                      \
        _Pragma("unroll")                                                       \
        for (int i_ = tid; i_ < 1280; i_ += 256)                                \
            CP_ASYNC16(bdst_ + i_ * 16, bsrc_ + (size_t)i_ * 16);               \
        if (ASRC == 0) {                                                        \
            _Pragma("unroll")                                                   \
            for (int i_ = tid; i_ < 640; i_ += 256) {                           \
                const int p_ = i_ / 320, l_ = i_ - p_ * 320;                    \
                const char* asrc_ = Apack +                                     \
                    ((size_t)(p_ * 8 + (c_)) * Mtot + m0) * 80 + (size_t)l_ * 16; \
                CP_ASYNC16(sb0 + (buf_) * STG + p_ * SA_LO + l_ * 16, asrc_);   \
            }                                                                   \
        }                                                                       \
        CP_COMMIT();                                                            \
    } while (0)

    ISSUE_CHUNK(0, 0);
    ISSUE_CHUNK(1, 1);

    for (int c = 0; c < 8; ++c) {
        const int buf = c % 3;
        if (c < 6) CP_WAIT1(); else CP_WAIT0();
        __syncthreads();
        if (c + 2 < 8) ISSUE_CHUNK(c + 2, (c + 2) % 3);

        if (ASRC == 1) {
            float v[8];
#pragma unroll
            for (int i = 0; i < 8; ++i) {
                const int k = c * 32 + kq + i;
                float h = fmaf(dd.x, W1[k], fmaf(dd.y, W1[256 + k], fmaf(dd.z, W1[512 + k], b1[k])));
                v[i] = fmaxf(h, 0.f);
            }
            uint4 h0, l0;
            split2(v[0], v[1], h0.x, l0.x); split2(v[2], v[3], h0.y, l0.y);
            split2(v[4], v[5], h0.z, l0.z); split2(v[6], v[7], h0.w, l0.w);
            char* stc = smem_dyn + buf * STG;
            *(uint4*)(stc + arow * 80 + kq * 2)         = h0;
            *(uint4*)(stc + SA_LO + arow * 80 + kq * 2) = l0;
            __syncthreads();
        }

        const uint32_t sb = sb0 + buf * STG;
#pragma unroll
        for (int ks = 0; ks < 2; ++ks) {
            uint32_t ah[2][4], al[2][4];
#pragma unroll
            for (int mt = 0; mt < 2; ++mt) {
                const uint32_t ra = sb + (uint32_t)(warp_m * 32 + mt * 16 + (lane & 15)) * 80
                                  + ks * 32 + ((lane >> 4) << 4);
                LDM_X4(ah[mt][0], ah[mt][1], ah[mt][2], ah[mt][3], ra);
                LDM_X4(al[mt][0], al[mt][1], al[mt][2], al[mt][3], ra + SA_LO);
            }
            uint32_t bh[4][2], bl[4][2];
#pragma unroll
            for (int np = 0; np < 2; ++np) {
                const uint32_t rb = sb + SB_HI
                                  + (uint32_t)(warp_n * 32 + np * 16 + (lane & 7) + ((lane >> 4) << 3)) * 80
                                  + ks * 32 + ((lane & 8) ? 16 : 0);
                LDM_X4(bh[2 * np][0], bh[2 * np][1], bh[2 * np + 1][0], bh[2 * np + 1][1], rb);
                LDM_X4(bl[2 * np][0], bl[2 * np][1], bl[2 * np + 1][0], bl[2 * np + 1][1], rb + 10240);
            }
#pragma unroll
            for (int mt = 0; mt < 2; ++mt)
#pragma unroll
                for (int nt = 0; nt < 4; ++nt) {
                    MMA16816(acc[mt][nt], ah[mt], bh[nt]);
                    MMA16816(acc[mt][nt], ah[mt], bl[nt]);
                    MMA16816(acc[mt][nt], al[mt], bh[nt]);
                }
        }
    }
#undef ISSUE_CHUNK

    // ---- epilogue ----
    const size_t r_base = m0 + warp_m * 32 + (lane >> 2);
    const int c_base = n0 + warp_n * 32 + (lane & 3) * 2;
#pragma unroll
    for (int mt = 0; mt < 2; ++mt) {
#pragma unroll
        for (int half = 0; half < 2; ++half) {
            const size_t row = r_base + mt * 16 + half * 8;
            const float* gat = nullptr;
            const float* qg1 = nullptr;
            size_t grow = row;
            if (EPI == 2) {
                const size_t bq = row / 24;
                const int j = (int)(row % 24);
                const int b = (int)(bq >> 12);
                grow = bq * NB + j;
                if (gsel == 0) {
                    if (j < KNN_K)
                        gat = g_vp + ((size_t)(b * NPTS) + g_knn[bq * KNN_K + j]) * 256;
                    else
                        gat = g_gv + (bq * KG2 + (j - KNN_K)) * 256;
                } else {
                    if (j < KNN_K)
                        gat = g_kp + ((size_t)(b * NPTS) + g_knn[bq * KNN_K + j]) * 256;
                    else
                        gat = g_gk + (bq * KG2 + (j - KNN_K)) * 256;
                    qg1 = g_qag1 + b * 256;
                }
            }
#pragma unroll
            for (int nt = 0; nt < 4; ++nt) {
                const int col = c_base + nt * 8;
                float ox = acc[mt][nt][half * 2 + 0];
                float oy = acc[mt][nt][half * 2 + 1];
                if (EPI == 0) {
                    if (bias) {
                        const float2 bv = *(const float2*)(bias + col);
                        ox += bv.x; oy += bv.y;
                    }
                    float* C = gsel ? C1 : C0;
                    *(float2*)(C + row * 256 + col) = make_float2(ox, oy);
                } else {
                    if (gsel == 0) {
                        // V = gathered v + pos (pos = acc + db2)
                        const float2 bv = *(const float2*)(bias + col);
                        const float2 vv = *(const float2*)(gat + col);
                        *(float2*)(g_V + grow * 256 + col) =
                            make_float2(vv.x + ox + bv.x, vv.y + oy + bv.y);
                    } else {
                        // A1 = relu(qag1 - kg1 + acc + cvec) -> packed
                        const float2 kk = *(const float2*)(gat + col);
                        const float2 qq = *(const float2*)(qg1 + col);
                        const float2 cv = *(const float2*)(g_cvec + col);
                        float ga = fmaxf(qq.x - kk.x + ox + cv.x, 0.f);
                        float gb = fmaxf(qq.y - kk.y + oy + cv.y, 0.f);
                        uint32_t h, l;
                        split2(ga, gb, h, l);
                        const int chunk = col >> 5, within = col & 31;
                        *(uint32_t*)(g_A1pack + pk_off(0, chunk, XROWS, grow, within)) = h;
                        *(uint32_t*)(g_A1pack + pk_off(1, chunk, XROWS, grow, within)) = l;
                    }
                }
            }
        }
    }
}

// ---------------- final: per-channel softmax over 25 neighbors, dot with V ------
__global__ __launch_bounds__(256)
void final_kernel(float* __restrict__ out) {
    const int bq = blockIdx.x;
    const int f  = threadIdx.x;
    const size_t base = (size_t)bq * NB * DIM + f;
    float a[NB];
#pragma unroll
    for (int j = 0; j < NB; ++j) a[j] = g_Xf[base + j * DIM];
    float m = a[0];
#pragma unroll
    for (int j = 1; j < NB; ++j) m = fmaxf(m, a[j]);
    float s = 0.f, o = 0.f;
#pragma unroll
    for (int j = 0; j < NB; ++j) {
        const float w = expf(a[j] - m);
        s += w;
        o = fmaf(w, g_V[base + j * DIM], o);
    }
    out[(size_t)bq * DIM + f] = o / s;
}

// ---------------- launch ----------------
extern "C" void kernel_launch(void* const* d_in, const int* in_sizes, int n_in,
                              void* d_out, int out_size) {
    const float* xyz_q  = (const float*)d_in[0];
    const float* lat    = (const float*)d_in[1];
    const float* xyz    = (const float*)d_in[2];
    const float* points = (const float*)d_in[3];
    const float* sgf    = (const float*)d_in[4];
    const float* closest= (const float*)d_in[5];
    const float* w_qs   = (const float*)d_in[6];
    const float* w_ks   = (const float*)d_in[7];
    const float* w_vs   = (const float*)d_in[8];
    const float* w_kc   = (const float*)d_in[9];
    const float* w_vc   = (const float*)d_in[10];
    const float* w_vg   = (const float*)d_in[12];
    const float* w_kg   = (const float*)d_in[11];
    const float* dw1    = (const float*)d_in[13];
    const float* db1    = (const float*)d_in[14];
    const float* dw2    = (const float*)d_in[15];
    const float* db2    = (const float*)d_in[16];
    const float* gw1    = (const float*)d_in[17];
    const float* gb1    = (const float*)d_in[18];
    const float* gw2    = (const float*)d_in[19];
    const float* gb2    = (const float*)d_in[20];

    float *kp, *vp, *gk, *gv, *Xf, *Wc;
    char *Ppk, *Spk, *A1pk;
    cudaGetSymbolAddress((void**)&kp,   g_kp);
    cudaGetSymbolAddress((void**)&vp,   g_vp);
    cudaGetSymbolAddress((void**)&gk,   g_gk);
    cudaGetSymbolAddress((void**)&gv,   g_gv);
    cudaGetSymbolAddress((void**)&Xf,   g_Xf);
    cudaGetSymbolAddress((void**)&Wc,   g_Wc);
    cudaGetSymbolAddress((void**)&Ppk,  g_Ppack);
    cudaGetSymbolAddress((void**)&Spk,  g_Spack);
    cudaGetSymbolAddress((void**)&A1pk, g_A1pack);

    cudaFuncSetAttribute(gemm_cp_kernel<0, 0, 1>, cudaFuncAttributeMaxDynamicSharedMemorySize, SMEM_DYN);
    cudaFuncSetAttribute(gemm_cp_kernel<1, 2, 1>, cudaFuncAttributeMaxDynamicSharedMemorySize, SMEM_DYN);
    cudaFuncSetAttribute(gemm_cp_kernel<0, 0, 0>, cudaFuncAttributeMaxDynamicSharedMemorySize, SMEM_DYN);

    // combined weights (fp32): Wc0 = w_ks@gw1, Wc1 = w_kc@gw1, Wc2 = dw2@gw1
    wcomb_kernel<<<dim3(4, 4, 3), 256>>>(w_ks, w_kc, dw2, gw1);
    // B slots: 0=w_ks@gw1 1=w_vs 2=w_kc@gw1 3=w_vc 4=dw2 5=dw2@gw1 6=gw2
    prepack_kernel<<<112, 256>>>(Wc, w_vs, Wc + 65536, w_vc, dw2, Wc + 131072, gw2);
    pack_a_kernel<<<(BATCH * NPTS) / 2, 256>>>(points, Ppk, BATCH * NPTS);
    pack_a_kernel<<<(BATCH * NQ * KG2) / 2, 256>>>(sgf, Spk, BATCH * NQ * KG2);

    knn_kernel<<<dim3(NQ / 8, BATCH), 256>>>(xyz_q, xyz);
    proj_small_kernel<<<BATCH, 256>>>(lat, w_qs, w_kg, w_vg);
    proj2_kernel<<<BATCH, 256>>>(gw1, gb1, db2);

    // dual-weight projections: points -> (kg1, vp), sgf -> (gkg1, gv)
    gemm_cp_kernel<0, 0, 1><<<dim3((BATCH * NPTS) / 64, 4), 256, SMEM_DYN>>>(
        Ppk, BATCH * NPTS, 0, nullptr, kp, vp, nullptr, nullptr);
    gemm_cp_kernel<0, 0, 1><<<dim3((BATCH * NQ * KG2) / 64, 4), 256, SMEM_DYN>>>(
        Spk, BATCH * NQ * KG2, 2, nullptr, gk, gv, nullptr, nullptr);

    db_kernel<<<BATCH * NQ, 256>>>(xyz_q, xyz, closest);

    // hidden GEMM: relu(d@dw1+b1) @ {dw2, dw2@gw1}; epilogue writes V + packed A1
    gemm_cp_kernel<1, 2, 1><<<dim3(POSROWS / 64, 4), 256, SMEM_DYN>>>(
        nullptr, POSROWS, 4, db2, nullptr, nullptr, dw1, db1);

    // gamma2
    gemm_cp_kernel<0, 0, 0><<<dim3(XROWS / 64, 2), 256, SMEM_DYN>>>(
        A1pk, XROWS, 6, gb2, Xf, nullptr, nullptr, nullptr);

    final_kernel<<<BATCH * NQ, 256>>>((float*)d_out);
}